// round 4
// baseline (speedup 1.0000x reference)
#include <cuda_runtime.h>
#include <math.h>
#include <float.h>

#define BB 2
#define SS 2048
#define EE 1024
#define HH 16
#define DD 64

// Packed fp32x2 ops (Blackwell sm_103a; ptxas never auto-fuses these)
#define FMA_F32X2(d, a, b, c) \
    asm("fma.rn.f32x2 %0, %1, %2, %3;" : "=l"(d) : "l"(a), "l"(b), "l"(c))
#define PACK_F32X2(out, lo, hi) \
    asm("mov.b64 %0, {%1, %2};" : "=l"(out) : "f"(lo), "f"(hi))
#define UNPACK_F32X2(lo, hi, in) \
    asm("mov.b64 {%0, %1}, %2;" : "=f"(lo), "=f"(hi) : "l"(in))

// Scratch (no allocations allowed): Q, K, V post-projection, fp32.
__device__ float g_q[BB * SS * EE];
__device__ float g_k[BB * SS * EE];
__device__ float g_v[BB * SS * EE];

// ---------------------------------------------------------------------------
// QKV projection: C[m,n] = sum_k X[m,k] * W[n,k] + bias[n]
// M=4096, N=1024, K=1024.  blockIdx.z selects {Q,K,V}.
// 128x128 tile, BK=8, 256 threads, 8x8 micro-tile, double-buffered smem.
// Inner product via fma.rn.f32x2: acc packed in (j,j+1) pairs; B operand
// pairs come pre-packed from 16B shared loads; A broadcast packed per kk
// on the ALU pipe (parallel to FMA pipe).
// ---------------------------------------------------------------------------
__global__ __launch_bounds__(256) void qkv_gemm_kernel(
    const float* __restrict__ x,
    const float* __restrict__ Wq, const float* __restrict__ bq,
    const float* __restrict__ Wk, const float* __restrict__ bk,
    const float* __restrict__ Wv, const float* __restrict__ bv)
{
    __shared__ __align__(16) float As[2][8][128];   // [buf][k][m]
    __shared__ __align__(16) float Bs[2][8][128];   // [buf][k][n]

    const float* W; const float* bias; float* outp;
    if (blockIdx.z == 0)      { W = Wq; bias = bq; outp = g_q; }
    else if (blockIdx.z == 1) { W = Wk; bias = bk; outp = g_k; }
    else                      { W = Wv; bias = bv; outp = g_v; }

    const int tid = threadIdx.x;
    const int tx = tid & 15, ty = tid >> 4;
    const int m0 = blockIdx.y * 128, n0 = blockIdx.x * 128;
    const int lr = tid >> 1;          // 0..127: tile row (m for A, n for B)
    const int lk = (tid & 1) << 2;    // 0 or 4: k offset within BK=8

    const float* xp = x + (size_t)(m0 + lr) * EE + lk;
    const float* wp = W + (size_t)(n0 + lr) * EE + lk;

    // acc packed: accp[i][jp] = (acc[i][2jp], acc[i][2jp+1])
    unsigned long long accp[8][4];
#pragma unroll
    for (int i = 0; i < 8; i++)
#pragma unroll
        for (int jp = 0; jp < 4; jp++) accp[i][jp] = 0ULL;

    // Prologue: k-step 0 into buffer 0
    {
        float4 a4 = *(const float4*)(xp);
        float4 b4 = *(const float4*)(wp);
        As[0][lk + 0][lr] = a4.x; As[0][lk + 1][lr] = a4.y;
        As[0][lk + 2][lr] = a4.z; As[0][lk + 3][lr] = a4.w;
        Bs[0][lk + 0][lr] = b4.x; Bs[0][lk + 1][lr] = b4.y;
        Bs[0][lk + 2][lr] = b4.z; Bs[0][lk + 3][lr] = b4.w;
    }
    __syncthreads();

    int buf = 0;
    for (int k0 = 8; k0 <= EE; k0 += 8) {
        float4 na, nb;
        const bool more = (k0 < EE);
        if (more) {                         // prefetch next k-step to registers
            na = *(const float4*)(xp + k0);
            nb = *(const float4*)(wp + k0);
        }

#pragma unroll
        for (int kk = 0; kk < 8; kk++) {
            float4 av0 = *(const float4*)(&As[buf][kk][ty << 3]);
            float4 av1 = *(const float4*)(&As[buf][kk][(ty << 3) + 4]);
            // B pairs pre-packed: two adjacent fp32 = one f32x2 operand
            ulonglong2 bq0 = *(const ulonglong2*)(&Bs[buf][kk][tx << 3]);
            ulonglong2 bq1 = *(const ulonglong2*)(&Bs[buf][kk][(tx << 3) + 4]);
            unsigned long long bp[4] = {bq0.x, bq0.y, bq1.x, bq1.y};
            float a[8] = {av0.x, av0.y, av0.z, av0.w,
                          av1.x, av1.y, av1.z, av1.w};
#pragma unroll
            for (int i = 0; i < 8; i++) {
                unsigned long long ap;
                PACK_F32X2(ap, a[i], a[i]);          // ALU pipe, hidden
                FMA_F32X2(accp[i][0], ap, bp[0], accp[i][0]);
                FMA_F32X2(accp[i][1], ap, bp[1], accp[i][1]);
                FMA_F32X2(accp[i][2], ap, bp[2], accp[i][2]);
                FMA_F32X2(accp[i][3], ap, bp[3], accp[i][3]);
            }
        }

        if (more) {                         // fill the other buffer, single sync
            buf ^= 1;
            As[buf][lk + 0][lr] = na.x; As[buf][lk + 1][lr] = na.y;
            As[buf][lk + 2][lr] = na.z; As[buf][lk + 3][lr] = na.w;
            Bs[buf][lk + 0][lr] = nb.x; Bs[buf][lk + 1][lr] = nb.y;
            Bs[buf][lk + 2][lr] = nb.z; Bs[buf][lk + 3][lr] = nb.w;
            __syncthreads();
        }
    }

    // Epilogue: unpack, bias add, coalesced float4 stores
    float bb[8];
#pragma unroll
    for (int j = 0; j < 8; j++) bb[j] = bias[n0 + (tx << 3) + j];
#pragma unroll
    for (int i = 0; i < 8; i++) {
        float c[8];
#pragma unroll
        for (int jp = 0; jp < 4; jp++)
            UNPACK_F32X2(c[2 * jp], c[2 * jp + 1], accp[i][jp]);
        float* op = outp + (size_t)(m0 + (ty << 3) + i) * EE + n0 + (tx << 3);
        float4 o0, o1;
        o0.x = c[0] + bb[0]; o0.y = c[1] + bb[1];
        o0.z = c[2] + bb[2]; o0.w = c[3] + bb[3];
        o1.x = c[4] + bb[4]; o1.y = c[5] + bb[5];
        o1.z = c[6] + bb[6]; o1.w = c[7] + bb[7];
        *(float4*)(op)     = o0;
        *(float4*)(op + 4) = o1;
    }
}

// ---------------------------------------------------------------------------
// RoPE applied in-place to g_q and g_k.
// One thread per (b, s, h, i) with i in [0,32): handles the (i, i+32) pair.
// Angles computed in double (args up to ~2047 rad: immune to fast-math sinf).
// ---------------------------------------------------------------------------
__global__ __launch_bounds__(256) void rope_kernel()
{
    const int total = BB * SS * HH * (DD / 2);
    int idx = blockIdx.x * 256 + threadIdx.x;
    if (idx >= total) return;
    int i = idx & 31;
    int h = (idx >> 5) & (HH - 1);
    int s = (idx >> 9) & (SS - 1);
    int b = idx >> 20;

    double ang = (double)s * exp(-(double)i * (log(10000.0) / 32.0));
    float c  = (float)cos(ang);
    float sn = (float)sin(ang);

    size_t base = (size_t)(b * SS + s) * EE + h * DD;
    float q1 = g_q[base + i], q2 = g_q[base + i + 32];
    g_q[base + i]      = q1 * c - q2 * sn;
    g_q[base + i + 32] = q2 * c + q1 * sn;
    float k1 = g_k[base + i], k2 = g_k[base + i + 32];
    g_k[base + i]      = k1 * c - k2 * sn;
    g_k[base + i + 32] = k2 * c + k1 * sn;
}

// ---------------------------------------------------------------------------
// Flash attention, fp32. One block per (b, h, 64-query tile).
// 256 threads (16x16), 4x4 micro-tiles; online softmax; P staged via smem.
// Dynamic smem: Qs[d][r] 16KB, Ks[d][c] 16KB, Vs[c][d] 16KB, Ps[r][c] 16KB.
// ---------------------------------------------------------------------------
__global__ __launch_bounds__(256) void attn_kernel(
    const float* __restrict__ mask, float* __restrict__ out)
{
    extern __shared__ float smem[];
    float* Qs = smem;              // [64][64] d-major:  Qs[d*64 + r]
    float* Ks = smem + 4096;       // [64][64] d-major:  Ks[d*64 + c]
    float* Vs = smem + 8192;       // [64][64] k-major:  Vs[c*64 + d]
    float* Ps = smem + 12288;      // [64][64] r-major:  Ps[r*64 + c]

    const int tid = threadIdx.x;
    const int tx = tid & 15, ty = tid >> 4;
    const int b = blockIdx.z, h = blockIdx.y;
    const int q0 = blockIdx.x * 64;

    const float* qb = g_q + (size_t)b * SS * EE + h * DD;
    const float* kb = g_k + (size_t)b * SS * EE + h * DD;
    const float* vb = g_v + (size_t)b * SS * EE + h * DD;
    const float* mrow = mask + (size_t)b * SS;

    // Load Q tile transposed into Qs[d][r]  (r-fast mapping: conflict-free stores)
    {
        int r = tid & 15, dc = (tid >> 4) << 2;
#pragma unroll
        for (int p = 0; p < 4; p++) {
            int rr = r + p * 16;
            float4 v4 = *(const float4*)(qb + (size_t)(q0 + rr) * EE + dc);
            Qs[(dc + 0) * 64 + rr] = v4.x; Qs[(dc + 1) * 64 + rr] = v4.y;
            Qs[(dc + 2) * 64 + rr] = v4.z; Qs[(dc + 3) * 64 + rr] = v4.w;
        }
    }

    float mi[4], li[4], acc[4][4];
#pragma unroll
    for (int i = 0; i < 4; i++) {
        mi[i] = -FLT_MAX; li[i] = 0.f;
#pragma unroll
        for (int j = 0; j < 4; j++) acc[i][j] = 0.f;
    }
    __syncthreads();

    for (int k0 = 0; k0 < SS; k0 += 64) {
        // K tile transposed (r-fast), V tile row-major (coalesced)
        {
            int r = tid & 15, dc = (tid >> 4) << 2;
#pragma unroll
            for (int p = 0; p < 4; p++) {
                int rr = r + p * 16;
                float4 v4 = *(const float4*)(kb + (size_t)(k0 + rr) * EE + dc);
                Ks[(dc + 0) * 64 + rr] = v4.x; Ks[(dc + 1) * 64 + rr] = v4.y;
                Ks[(dc + 2) * 64 + rr] = v4.z; Ks[(dc + 3) * 64 + rr] = v4.w;
            }
        }
        {
            int r = tid >> 4, dc = (tid & 15) << 2;
#pragma unroll
            for (int p = 0; p < 4; p++) {
                int rr = r + p * 16;
                *(float4*)(Vs + rr * 64 + dc) =
                    *(const float4*)(vb + (size_t)(k0 + rr) * EE + dc);
            }
        }
        __syncthreads();

        // S = Q K^T  (64x64 scores, 4x4 per thread)
        float sv[4][4];
#pragma unroll
        for (int i = 0; i < 4; i++)
#pragma unroll
            for (int j = 0; j < 4; j++) sv[i][j] = 0.f;
#pragma unroll 8
        for (int dd = 0; dd < 64; dd++) {
            float4 av = *(const float4*)(Qs + dd * 64 + (ty << 2));
            float4 bv = *(const float4*)(Ks + dd * 64 + (tx << 2));
            float a[4] = {av.x, av.y, av.z, av.w};
            float c[4] = {bv.x, bv.y, bv.z, bv.w};
#pragma unroll
            for (int i = 0; i < 4; i++)
#pragma unroll
                for (int j = 0; j < 4; j++) sv[i][j] = fmaf(a[i], c[j], sv[i][j]);
        }

        // scale + additive mask
        float mk[4];
#pragma unroll
        for (int j = 0; j < 4; j++) mk[j] = mrow[k0 + (tx << 2) + j];
#pragma unroll
        for (int i = 0; i < 4; i++)
#pragma unroll
            for (int j = 0; j < 4; j++) sv[i][j] = sv[i][j] * 0.125f + mk[j];

        // Online softmax (rows spread across the 16 lanes of a half-warp)
#pragma unroll
        for (int i = 0; i < 4; i++) {
            float rmax = fmaxf(fmaxf(sv[i][0], sv[i][1]), fmaxf(sv[i][2], sv[i][3]));
#pragma unroll
            for (int off = 8; off; off >>= 1)
                rmax = fmaxf(rmax, __shfl_xor_sync(0xffffffffu, rmax, off));
            float mnew = fmaxf(mi[i], rmax);
            float corr = __expf(mi[i] - mnew);
            float rsum = 0.f;
#pragma unroll
            for (int j = 0; j < 4; j++) {
                float p = __expf(sv[i][j] - mnew);
                sv[i][j] = p;
                rsum += p;
            }
#pragma unroll
            for (int off = 8; off; off >>= 1)
                rsum += __shfl_xor_sync(0xffffffffu, rsum, off);
            li[i] = li[i] * corr + rsum;
            mi[i] = mnew;
#pragma unroll
            for (int j = 0; j < 4; j++) acc[i][j] *= corr;
        }

        // Stage P (r-major), then O += P * V
#pragma unroll
        for (int i = 0; i < 4; i++)
            *(float4*)(Ps + ((ty << 2) + i) * 64 + (tx << 2)) =
                make_float4(sv[i][0], sv[i][1], sv[i][2], sv[i][3]);
        __syncthreads();

#pragma unroll 8
        for (int kk = 0; kk < 64; kk++) {
            float4 bv = *(const float4*)(Vs + kk * 64 + (tx << 2));
#pragma unroll
            for (int i = 0; i < 4; i++) {
                float a = Ps[((ty << 2) + i) * 64 + kk];   // broadcast
                acc[i][0] = fmaf(a, bv.x, acc[i][0]);
                acc[i][1] = fmaf(a, bv.y, acc[i][1]);
                acc[i][2] = fmaf(a, bv.z, acc[i][2]);
                acc[i][3] = fmaf(a, bv.w, acc[i][3]);
            }
        }
        __syncthreads();
    }

    // Epilogue: normalize and write out[b, q, h, d]
#pragma unroll
    for (int i = 0; i < 4; i++) {
        float inv = 1.0f / li[i];
        float4 o;
        o.x = acc[i][0] * inv; o.y = acc[i][1] * inv;
        o.z = acc[i][2] * inv; o.w = acc[i][3] * inv;
        *(float4*)(out + (size_t)(b * SS + q0 + (ty << 2) + i) * EE
                       + h * DD + (tx << 2)) = o;
    }
}

// ---------------------------------------------------------------------------
extern "C" void kernel_launch(void* const* d_in, const int* in_sizes, int n_in,
                              void* d_out, int out_size)
{
    const float* x    = (const float*)d_in[0];
    const float* mask = (const float*)d_in[1];
    const float* Wq   = (const float*)d_in[2];
    const float* bq   = (const float*)d_in[3];
    const float* Wk   = (const float*)d_in[4];
    const float* bk   = (const float*)d_in[5];
    const float* Wv   = (const float*)d_in[6];
    const float* bv   = (const float*)d_in[7];
    float* out = (float*)d_out;

    // QKV projections (+bias): 128x128 tiles, f32x2 inner product
    dim3 gg(EE / 128, (BB * SS) / 128, 3);
    qkv_gemm_kernel<<<gg, 256>>>(x, Wq, bq, Wk, bk, Wv, bv);

    // RoPE in-place on Q, K
    int nrope = BB * SS * HH * (DD / 2);
    rope_kernel<<<(nrope + 255) / 256, 256>>>();

    // Flash attention (64KB dynamic smem -> opt-in; idempotent, graph-safe)
    cudaFuncSetAttribute(attn_kernel,
                         cudaFuncAttributeMaxDynamicSharedMemorySize, 65536);
    dim3 ga(SS / 64, HH, BB);
    attn_kernel<<<ga, 256, 65536>>>(mask, out);
}

// round 10
// speedup vs baseline: 1.2621x; 1.2621x over previous
#include <cuda_runtime.h>
#include <math.h>
#include <float.h>

#define BB 2
#define SS 2048
#define EE 1024
#define HH 16
#define DD 64

// Packed fp32x2 ops (Blackwell sm_103a; ptxas never auto-fuses these)
#define FMA_F32X2(d, a, b, c) \
    asm("fma.rn.f32x2 %0, %1, %2, %3;" : "=l"(d) : "l"(a), "l"(b), "l"(c))
#define MUL_F32X2(d, a, b) \
    asm("mul.rn.f32x2 %0, %1, %2;" : "=l"(d) : "l"(a), "l"(b))
#define PACK_F32X2(out, lo, hi) \
    asm("mov.b64 %0, {%1, %2};" : "=l"(out) : "f"(lo), "f"(hi))
#define UNPACK_F32X2(lo, hi, in) \
    asm("mov.b64 {%0, %1}, %2;" : "=f"(lo), "=f"(hi) : "l"(in))

// Scratch (no allocations allowed): Q, K, V post-projection, fp32.
__device__ float g_q[BB * SS * EE];
__device__ float g_k[BB * SS * EE];
__device__ float g_v[BB * SS * EE];
// RoPE cos/sin tables: angle depends only on (s, i), i in [0,32)
__device__ float g_cos[SS * 32];
__device__ float g_sin[SS * 32];

// ---------------------------------------------------------------------------
// QKV projection (measured R4: 669us, 38.6 TF/s effective).
// ---------------------------------------------------------------------------
__global__ __launch_bounds__(256) void qkv_gemm_kernel(
    const float* __restrict__ x,
    const float* __restrict__ Wq, const float* __restrict__ bq,
    const float* __restrict__ Wk, const float* __restrict__ bk,
    const float* __restrict__ Wv, const float* __restrict__ bv)
{
    __shared__ __align__(16) float As[2][8][128];   // [buf][k][m]
    __shared__ __align__(16) float Bs[2][8][128];   // [buf][k][n]

    const float* W; const float* bias; float* outp;
    if (blockIdx.z == 0)      { W = Wq; bias = bq; outp = g_q; }
    else if (blockIdx.z == 1) { W = Wk; bias = bk; outp = g_k; }
    else                      { W = Wv; bias = bv; outp = g_v; }

    const int tid = threadIdx.x;
    const int tx = tid & 15, ty = tid >> 4;
    const int m0 = blockIdx.y * 128, n0 = blockIdx.x * 128;
    const int lr = tid >> 1;
    const int lk = (tid & 1) << 2;

    const float* xp = x + (size_t)(m0 + lr) * EE + lk;
    const float* wp = W + (size_t)(n0 + lr) * EE + lk;

    unsigned long long accp[8][4];
#pragma unroll
    for (int i = 0; i < 8; i++)
#pragma unroll
        for (int jp = 0; jp < 4; jp++) accp[i][jp] = 0ULL;

    {
        float4 a4 = *(const float4*)(xp);
        float4 b4 = *(const float4*)(wp);
        As[0][lk + 0][lr] = a4.x; As[0][lk + 1][lr] = a4.y;
        As[0][lk + 2][lr] = a4.z; As[0][lk + 3][lr] = a4.w;
        Bs[0][lk + 0][lr] = b4.x; Bs[0][lk + 1][lr] = b4.y;
        Bs[0][lk + 2][lr] = b4.z; Bs[0][lk + 3][lr] = b4.w;
    }
    __syncthreads();

    int buf = 0;
    for (int k0 = 8; k0 <= EE; k0 += 8) {
        float4 na, nb;
        const bool more = (k0 < EE);
        if (more) {
            na = *(const float4*)(xp + k0);
            nb = *(const float4*)(wp + k0);
        }

#pragma unroll
        for (int kk = 0; kk < 8; kk++) {
            float4 av0 = *(const float4*)(&As[buf][kk][ty << 3]);
            float4 av1 = *(const float4*)(&As[buf][kk][(ty << 3) + 4]);
            ulonglong2 bq0 = *(const ulonglong2*)(&Bs[buf][kk][tx << 3]);
            ulonglong2 bq1 = *(const ulonglong2*)(&Bs[buf][kk][(tx << 3) + 4]);
            unsigned long long bp[4] = {bq0.x, bq0.y, bq1.x, bq1.y};
            float a[8] = {av0.x, av0.y, av0.z, av0.w,
                          av1.x, av1.y, av1.z, av1.w};
#pragma unroll
            for (int i = 0; i < 8; i++) {
                unsigned long long ap;
                PACK_F32X2(ap, a[i], a[i]);
                FMA_F32X2(accp[i][0], ap, bp[0], accp[i][0]);
                FMA_F32X2(accp[i][1], ap, bp[1], accp[i][1]);
                FMA_F32X2(accp[i][2], ap, bp[2], accp[i][2]);
                FMA_F32X2(accp[i][3], ap, bp[3], accp[i][3]);
            }
        }

        if (more) {
            buf ^= 1;
            As[buf][lk + 0][lr] = na.x; As[buf][lk + 1][lr] = na.y;
            As[buf][lk + 2][lr] = na.z; As[buf][lk + 3][lr] = na.w;
            Bs[buf][lk + 0][lr] = nb.x; Bs[buf][lk + 1][lr] = nb.y;
            Bs[buf][lk + 2][lr] = nb.z; Bs[buf][lk + 3][lr] = nb.w;
            __syncthreads();
        }
    }

    float bb[8];
#pragma unroll
    for (int j = 0; j < 8; j++) bb[j] = bias[n0 + (tx << 3) + j];
#pragma unroll
    for (int i = 0; i < 8; i++) {
        float c[8];
#pragma unroll
        for (int jp = 0; jp < 4; jp++)
            UNPACK_F32X2(c[2 * jp], c[2 * jp + 1], accp[i][jp]);
        float* op = outp + (size_t)(m0 + (ty << 3) + i) * EE + n0 + (tx << 3);
        float4 o0, o1;
        o0.x = c[0] + bb[0]; o0.y = c[1] + bb[1];
        o0.z = c[2] + bb[2]; o0.w = c[3] + bb[3];
        o1.x = c[4] + bb[4]; o1.y = c[5] + bb[5];
        o1.z = c[6] + bb[6]; o1.w = c[7] + bb[7];
        *(float4*)(op)     = o0;
        *(float4*)(op + 4) = o1;
    }
}

// ---------------------------------------------------------------------------
// RoPE table init: 65536 unique (s, i) angles, double precision once.
// ---------------------------------------------------------------------------
__global__ __launch_bounds__(256) void rope_init_kernel()
{
    int idx = blockIdx.x * 256 + threadIdx.x;   // s*32 + i
    if (idx >= SS * 32) return;
    int i = idx & 31;
    int s = idx >> 5;
    double ang = (double)s * exp(-(double)i * (log(10000.0) / 32.0));
    g_cos[idx] = (float)cos(ang);
    g_sin[idx] = (float)sin(ang);
}

// ---------------------------------------------------------------------------
// RoPE apply (table-driven): pure memory op.
// ---------------------------------------------------------------------------
__global__ __launch_bounds__(256) void rope_kernel()
{
    const int total = BB * SS * HH * (DD / 2);
    int idx = blockIdx.x * 256 + threadIdx.x;
    if (idx >= total) return;
    int i = idx & 31;
    int h = (idx >> 5) & (HH - 1);
    int s = (idx >> 9) & (SS - 1);
    int b = idx >> 20;

    float c  = g_cos[(s << 5) + i];
    float sn = g_sin[(s << 5) + i];

    size_t base = (size_t)(b * SS + s) * EE + h * DD;
    float q1 = g_q[base + i], q2 = g_q[base + i + 32];
    g_q[base + i]      = q1 * c - q2 * sn;
    g_q[base + i + 32] = q2 * c + q1 * sn;
    float k1 = g_k[base + i], k2 = g_k[base + i + 32];
    g_k[base + i]      = k1 * c - k2 * sn;
    g_k[base + i + 32] = k2 * c + k1 * sn;
}

// ---------------------------------------------------------------------------
// Flash attention v2: 128-query x 64-key tiles, 256 threads, 8x4 microtile,
// f32x2 FMA in both GEMMs. Thread grid 16x16: ty -> 8 q-rows, tx -> 4 cols.
// smem (floats): Qs[64][128] d-major | Ks[64][64] d-major |
//                Vs[64][64] k-major  | Ps[64][132] transposed P (pad 4)
// ---------------------------------------------------------------------------
#define PSTRIDE 132

__global__ __launch_bounds__(256, 2) void attn_kernel(
    const float* __restrict__ mask, float* __restrict__ out)
{
    extern __shared__ __align__(16) float smem[];
    float* Qs = smem;              // [64][128]: Qs[d*128 + r]
    float* Ks = smem + 8192;       // [64][64]:  Ks[d*64 + c]
    float* Vs = smem + 12288;      // [64][64]:  Vs[kk*64 + d]
    float* Ps = smem + 16384;      // [64][132]: Ps[kk*132 + r]

    const int tid = threadIdx.x;
    const int tx = tid & 15, ty = tid >> 4;
    const int b = blockIdx.z, h = blockIdx.y;
    const int q0 = blockIdx.x * 128;

    const float* qb = g_q + (size_t)b * SS * EE + h * DD;
    const float* kb = g_k + (size_t)b * SS * EE + h * DD;
    const float* vb = g_v + (size_t)b * SS * EE + h * DD;
    const float* mrow = mask + (size_t)b * SS;

    // Load Q tile transposed: Qs[d][r], 128 rows x 64 d (once per block)
    {
        int r = tid >> 1;               // 0..127
        int c0 = (tid & 1) * 32;        // 0 or 32
#pragma unroll
        for (int j = 0; j < 8; j++) {
            int dc = c0 + j * 4;
            float4 v4 = *(const float4*)(qb + (size_t)(q0 + r) * EE + dc);
            Qs[(dc + 0) * 128 + r] = v4.x; Qs[(dc + 1) * 128 + r] = v4.y;
            Qs[(dc + 2) * 128 + r] = v4.z; Qs[(dc + 3) * 128 + r] = v4.w;
        }
    }

    float mi[8], li[8];
    unsigned long long accp[8][2];      // O accumulator, 8 rows x (2 f32x2 = 4 d)
#pragma unroll
    for (int i = 0; i < 8; i++) {
        mi[i] = -FLT_MAX; li[i] = 0.f;
        accp[i][0] = 0ULL; accp[i][1] = 0ULL;
    }
    __syncthreads();

    for (int k0 = 0; k0 < SS; k0 += 64) {
        // K tile transposed Ks[d][c]: 64 kpos x 64 d
        {
            int kp = tid & 63;
            int c0 = (tid >> 6) * 16;   // 0,16,32,48
#pragma unroll
            for (int j = 0; j < 4; j++) {
                int dc = c0 + j * 4;
                float4 v4 = *(const float4*)(kb + (size_t)(k0 + kp) * EE + dc);
                Ks[(dc + 0) * 64 + kp] = v4.x; Ks[(dc + 1) * 64 + kp] = v4.y;
                Ks[(dc + 2) * 64 + kp] = v4.z; Ks[(dc + 3) * 64 + kp] = v4.w;
            }
        }
        // V tile row-major copy: Vs[kk][d]
#pragma unroll
        for (int p = 0; p < 4; p++) {
            int lin = p * 256 + tid;
            int kp = lin >> 4, dc = (lin & 15) << 2;
            *(float4*)(Vs + kp * 64 + dc) =
                *(const float4*)(vb + (size_t)(k0 + kp) * EE + dc);
        }
        __syncthreads();

        // S = Q K^T : 8 rows x 4 cols per thread, f32x2-packed cols
        unsigned long long svp[8][2];
#pragma unroll
        for (int i = 0; i < 8; i++) { svp[i][0] = 0ULL; svp[i][1] = 0ULL; }
#pragma unroll 4
        for (int dd = 0; dd < 64; dd++) {
            float4 a0 = *(const float4*)(Qs + dd * 128 + (ty << 3));
            float4 a1 = *(const float4*)(Qs + dd * 128 + (ty << 3) + 4);
            ulonglong2 bq = *(const ulonglong2*)(Ks + dd * 64 + (tx << 2));
            float a[8] = {a0.x, a0.y, a0.z, a0.w, a1.x, a1.y, a1.z, a1.w};
#pragma unroll
            for (int i = 0; i < 8; i++) {
                unsigned long long ap;
                PACK_F32X2(ap, a[i], a[i]);
                FMA_F32X2(svp[i][0], ap, bq.x, svp[i][0]);
                FMA_F32X2(svp[i][1], ap, bq.y, svp[i][1]);
            }
        }

        // Softmax (online), P gathered column-wise for transposed stores
        float mk[4];
#pragma unroll
        for (int j = 0; j < 4; j++) mk[j] = mrow[k0 + (tx << 2) + j];

        float pv[4][8];
#pragma unroll
        for (int i = 0; i < 8; i++) {
            float s0, s1, s2, s3;
            UNPACK_F32X2(s0, s1, svp[i][0]);
            UNPACK_F32X2(s2, s3, svp[i][1]);
            s0 = s0 * 0.125f + mk[0]; s1 = s1 * 0.125f + mk[1];
            s2 = s2 * 0.125f + mk[2]; s3 = s3 * 0.125f + mk[3];
            float rmax = fmaxf(fmaxf(s0, s1), fmaxf(s2, s3));
#pragma unroll
            for (int off = 8; off; off >>= 1)
                rmax = fmaxf(rmax, __shfl_xor_sync(0xffffffffu, rmax, off));
            float mnew = fmaxf(mi[i], rmax);
            float corr = __expf(mi[i] - mnew);
            float p0 = __expf(s0 - mnew), p1 = __expf(s1 - mnew);
            float p2 = __expf(s2 - mnew), p3 = __expf(s3 - mnew);
            float rsum = p0 + p1 + p2 + p3;
#pragma unroll
            for (int off = 8; off; off >>= 1)
                rsum += __shfl_xor_sync(0xffffffffu, rsum, off);
            li[i] = li[i] * corr + rsum;
            mi[i] = mnew;
            unsigned long long cp;
            PACK_F32X2(cp, corr, corr);
            MUL_F32X2(accp[i][0], accp[i][0], cp);
            MUL_F32X2(accp[i][1], accp[i][1], cp);
            pv[0][i] = p0; pv[1][i] = p1; pv[2][i] = p2; pv[3][i] = p3;
        }

        // Stage P transposed: Ps[kcol][qrow]
#pragma unroll
        for (int j = 0; j < 4; j++) {
            float* pp = Ps + ((tx << 2) + j) * PSTRIDE + (ty << 3);
            *(float4*)(pp)     = make_float4(pv[j][0], pv[j][1], pv[j][2], pv[j][3]);
            *(float4*)(pp + 4) = make_float4(pv[j][4], pv[j][5], pv[j][6], pv[j][7]);
        }
        __syncthreads();

        // O += P V : same broadcast x packed-pair shape as QK^T
#pragma unroll 4
        for (int kk = 0; kk < 64; kk++) {
            float4 a0 = *(const float4*)(Ps + kk * PSTRIDE + (ty << 3));
            float4 a1 = *(const float4*)(Ps + kk * PSTRIDE + (ty << 3) + 4);
            ulonglong2 bq = *(const ulonglong2*)(Vs + kk * 64 + (tx << 2));
            float a[8] = {a0.x, a0.y, a0.z, a0.w, a1.x, a1.y, a1.z, a1.w};
#pragma unroll
            for (int i = 0; i < 8; i++) {
                unsigned long long ap;
                PACK_F32X2(ap, a[i], a[i]);
                FMA_F32X2(accp[i][0], ap, bq.x, accp[i][0]);
                FMA_F32X2(accp[i][1], ap, bq.y, accp[i][1]);
            }
        }
        __syncthreads();   // protect Ks/Vs/Ps before next iteration overwrites
    }

    // Epilogue: normalize, write out[b, q, h, d]
#pragma unroll
    for (int i = 0; i < 8; i++) {
        float inv = 1.0f / li[i];
        float c0, c1, c2, c3;
        UNPACK_F32X2(c0, c1, accp[i][0]);
        UNPACK_F32X2(c2, c3, accp[i][1]);
        float4 o;
        o.x = c0 * inv; o.y = c1 * inv; o.z = c2 * inv; o.w = c3 * inv;
        *(float4*)(out + (size_t)(b * SS + q0 + (ty << 3) + i) * EE
                       + h * DD + (tx << 2)) = o;
    }
}

// ---------------------------------------------------------------------------
extern "C" void kernel_launch(void* const* d_in, const int* in_sizes, int n_in,
                              void* d_out, int out_size)
{
    const float* x    = (const float*)d_in[0];
    const float* mask = (const float*)d_in[1];
    const float* Wq   = (const float*)d_in[2];
    const float* bq   = (const float*)d_in[3];
    const float* Wk   = (const float*)d_in[4];
    const float* bk   = (const float*)d_in[5];
    const float* Wv   = (const float*)d_in[6];
    const float* bv   = (const float*)d_in[7];
    float* out = (float*)d_out;

    // RoPE tables (independent of qkv_gemm -> overlaps on separate SMs)
    rope_init_kernel<<<(SS * 32 + 255) / 256, 256>>>();

    // QKV projections (+bias): 128x128 tiles, f32x2 inner product
    dim3 gg(EE / 128, (BB * SS) / 128, 3);
    qkv_gemm_kernel<<<gg, 256>>>(x, Wq, bq, Wk, bk, Wv, bv);

    // RoPE in-place on Q, K (table-driven)
    int nrope = BB * SS * HH * (DD / 2);
    rope_kernel<<<(nrope + 255) / 256, 256>>>();

    // Flash attention v2: 97KB dynamic smem (2 CTAs/SM), f32x2 GEMMs
    const int attn_smem = (8192 + 4096 + 4096 + 64 * PSTRIDE) * 4;  // 99328 B
    cudaFuncSetAttribute(attn_kernel,
                         cudaFuncAttributeMaxDynamicSharedMemorySize, attn_smem);
    dim3 ga(SS / 128, HH, BB);
    attn_kernel<<<ga, 256, attn_smem>>>(mask, out);
}